// round 14
// baseline (speedup 1.0000x reference)
#include <cuda_runtime.h>
#include <cuda_fp16.h>
#include <math.h>
#include <cstdint>

// Shapes: B=64, N=1024, F=4, H=128. BN = 65536 nodes.
// Output: pi [64,1024] then v [64,1] -> 65600 floats.
#define BN 65536
#define NT32 2048          // 32-node tiles
#define GRID_LOGITS 256    // x4 warps = 1024 -> exactly 2 tiles/warp

typedef unsigned long long ull;

__device__ float g_hx[128];
__device__ int g_cnt[64];

// ---------------- scalar helpers ----------------
__device__ __forceinline__ float tanh_fast(float x) {
    float r; asm("tanh.approx.f32 %0, %1;" : "=f"(r) : "f"(x)); return r;
}
// ---------------- packed f32x2 helpers ----------------
__device__ __forceinline__ ull pack2(float lo, float hi) {
    ull r; asm("mov.b64 %0, {%1, %2};" : "=l"(r) : "f"(lo), "f"(hi)); return r;
}
__device__ __forceinline__ void unpack2(ull p, float& lo, float& hi) {
    asm("mov.b64 {%0, %1}, %2;" : "=f"(lo), "=f"(hi) : "l"(p));
}
__device__ __forceinline__ ull fma2(ull a, ull b, ull c) {
    ull r; asm("fma.rn.f32x2 %0, %1, %2, %3;" : "=l"(r) : "l"(a), "l"(b), "l"(c)); return r;
}
__device__ __forceinline__ ull mul2(ull a, ull b) {
    ull r; asm("mul.rn.f32x2 %0, %1, %2;" : "=l"(r) : "l"(a), "l"(b)); return r;
}
__device__ __forceinline__ ull add2(ull a, ull b) {
    ull r; asm("add.rn.f32x2 %0, %1, %2;" : "=l"(r) : "l"(a), "l"(b)); return r;
}

// ---------------------------------------------------------------------------
// Kernel 0: fused gates + hx (+ counter reset). 32 blocks x 128 threads.
// One warp per h index; gates i, g, o only (f*c0 = 0).
// ---------------------------------------------------------------------------
__global__ void k_gh(const float* __restrict__ Wih, const float* __restrict__ bih,
                     const float* __restrict__ bhh, const float* __restrict__ q) {
    int t = threadIdx.x;
    if (blockIdx.x == 0 && t < 64) g_cnt[t] = 0;

    int lane = t & 31, wid = t >> 5;
    int h = blockIdx.x * 4 + wid;
    float4 qv = __ldg((const float4*)q + lane);

    int rows[3] = {h, 256 + h, 384 + h};
    float acc[3];
    #pragma unroll
    for (int i = 0; i < 3; i++) {
        float4 wv = __ldg((const float4*)(Wih + rows[i] * 128) + lane);
        acc[i] = wv.x * qv.x + wv.y * qv.y + wv.z * qv.z + wv.w * qv.w;
    }
    #pragma unroll
    for (int o = 16; o > 0; o >>= 1)
        #pragma unroll
        for (int i = 0; i < 3; i++)
            acc[i] += __shfl_xor_sync(0xffffffff, acc[i], o);

    if (lane == 0) {
        float ig = acc[0] + bih[h] + bhh[h];
        float gg = acc[1] + bih[256 + h] + bhh[256 + h];
        float og = acc[2] + bih[384 + h] + bhh[384 + h];
        float si = 1.f / (1.f + __expf(-ig));
        float so = 1.f / (1.f + __expf(-og));
        float cx = si * tanh_fast(gg);
        g_hx[h] = so * tanh_fast(cx);
    }
}

// ---------------------------------------------------------------------------
// Kernel 1: logits + FUSED softmax + v. Warp-autonomous 32-node x 128-h tiles.
// After a warp stores its tile, it bumps the row counter; the last arriver
// (32 tiles/row) performs the in-warp softmax for that row and writes v.
// ---------------------------------------------------------------------------
#define AH_STRIDE 72
#define AS_OFF   0        // 128*72 half2 = 9216 float-slots
#define ES_OFF   9216     // 4 warps x 32*72 half2 = 9216 float-slots
#define XS_OFF   18432    // 4 warps x 32 float4 = 512 floats
#define HXS_OFF  18944    // 128
#define VPS_OFF  19072    // 128
#define SM_FLOATS 19200   // 76.8 KB/CTA, x2 = 153.6 KB

__global__ __launch_bounds__(128, 2)
void k_logits(const float* __restrict__ nf, const float* __restrict__ Wemb,
              const float* __restrict__ bemb, const float* __restrict__ Wattn,
              const float* __restrict__ vparam, const float* __restrict__ Wval,
              const float* __restrict__ bval, float* __restrict__ out) {
    extern __shared__ float sm[];
    __half2* as2 = (__half2*)sm;              // [128][72]
    float* hxs   = sm + HXS_OFF;
    float* vps   = sm + VPS_OFF;

    int t = threadIdx.x;
    int lane = t & 31, w = t >> 5;
    int g = lane >> 2, tc = lane & 3;

    __half2* esw = (__half2*)(sm + ES_OFF) + w * (32 * AH_STRIDE);
    float4*  xsw = (float4*)(sm + XS_OFF) + w * 32;

    // ---- one-time staging: A = half2(W_attn), permuted k-pair columns ----
    for (int i = t * 4; i < 16384; i += 512) {
        float4 wv = *(const float4*)(Wattn + i);
        int h = i >> 7, k = i & 127;
        int k2 = k >> 1;
        int kb8 = k2 & ~7, j = k2 & 7;       // j in {0,2,4,6}
        int c1 = kb8 + ((j < 4) ? 2 * j : 2 * j - 7);
        as2[h * AH_STRIDE + c1]     = __floats2half2_rn(wv.x, wv.y);
        as2[h * AH_STRIDE + c1 + 2] = __floats2half2_rn(wv.z, wv.w);
    }
    hxs[t] = g_hx[t];
    vps[t] = vparam[t];

    // ---- per-lane embedding weights: TWO k2 pairs (lane, lane+32) ----
    ull w2[8], b2[2];
    int colL[2];
    #pragma unroll
    for (int p = 0; p < 2; p++) {
        int k2v = lane + p * 32;
        int kk = 2 * k2v;
        #pragma unroll
        for (int f = 0; f < 4; f++)
            w2[p * 4 + f] = pack2(Wemb[kk * 4 + f], Wemb[(kk + 1) * 4 + f]);
        b2[p] = pack2(bemb[kk], bemb[kk + 1]);
        int j = k2v & 7;
        colL[p] = (k2v & ~7) + ((j < 4) ? 2 * j : 2 * j - 7);
    }

    const ull C3 = pack2(-0.3333333333f, -0.3333333333f);
    const ull C5 = pack2(0.1333333333f, 0.1333333333f);
    const ull C7 = pack2(-0.0539682540f, -0.0539682540f);
    const __half2 hzero = __floats2half2_rn(0.f, 0.f);

    __syncthreads();   // as2 / hxs / vps ready (only block-wide sync)

    int gw = blockIdx.x * 4 + w;       // global warp id: 0..1023
    for (int tile = gw; tile < NT32; tile += GRID_LOGITS * 4) {
        int base = tile * 32;

        // ---- warp-private xs load (32 nodes) ----
        xsw[lane] = __ldg((const float4*)nf + (base + lane));
        __syncwarp();

        // ---- embedding: lane fills its two k2 columns for all 32 nodes ----
        #pragma unroll
        for (int n = 0; n < 32; n++) {
            float4 x = xsw[n];
            ull x0 = pack2(x.x, x.x), x1 = pack2(x.y, x.y);
            ull x2 = pack2(x.z, x.z), x3 = pack2(x.w, x.w);
            #pragma unroll
            for (int p = 0; p < 2; p++) {
                ull e = b2[p];
                e = fma2(x0, w2[p * 4 + 0], e);
                e = fma2(x1, w2[p * 4 + 1], e);
                e = fma2(x2, w2[p * 4 + 2], e);
                e = fma2(x3, w2[p * 4 + 3], e);
                float lo, hi;
                unpack2(e, lo, hi);
                esw[n * AH_STRIDE + colL[p]] =
                    __hmax2(__floats2half2_rn(lo, hi), hzero);
            }
        }
        __syncwarp();

        // ---- fp16 GEMM: warp tile 128h x 32n, K chunks of 16 ----
        float accr[8][4][4];
        #pragma unroll
        for (int mi = 0; mi < 8; mi++)
            #pragma unroll
            for (int ni = 0; ni < 4; ni++)
                #pragma unroll
                for (int j = 0; j < 4; j++) accr[mi][ni][j] = 0.f;

        #pragma unroll
        for (int kt = 0; kt < 8; kt++) {
            int cb = kt * 8 + 2 * tc;
            uint2 bfr[4];
            #pragma unroll
            for (int ni = 0; ni < 4; ni++) {
                int n = ni * 8 + g;
                bfr[ni] = *(const uint2*)(esw + n * AH_STRIDE + cb);
            }
            #pragma unroll
            for (int mi = 0; mi < 8; mi++) {
                int r = mi * 16 + g;
                uint2 alo = *(const uint2*)(as2 + r * AH_STRIDE + cb);
                uint2 ahi = *(const uint2*)(as2 + (r + 8) * AH_STRIDE + cb);
                #pragma unroll
                for (int ni = 0; ni < 4; ni++) {
                    asm volatile(
                        "mma.sync.aligned.m16n8k16.row.col.f32.f16.f16.f32 "
                        "{%0,%1,%2,%3}, {%4,%5,%6,%7}, {%8,%9}, {%0,%1,%2,%3};"
                        : "+f"(accr[mi][ni][0]), "+f"(accr[mi][ni][1]),
                          "+f"(accr[mi][ni][2]), "+f"(accr[mi][ni][3])
                        : "r"(alo.x), "r"(ahi.x), "r"(alo.y), "r"(ahi.y),
                          "r"(bfr[ni].x), "r"(bfr[ni].y));
                }
            }
        }

        // ---- epilogue: v-weighted tanh, h-sum fully warp-internal ----
        ull s2[4];
        #pragma unroll
        for (int ni = 0; ni < 4; ni++) s2[ni] = pack2(0.f, 0.f);
        #pragma unroll
        for (int mi = 0; mi < 8; mi++) {
            int h0 = mi * 16 + g;
            ull hxa = pack2(hxs[h0], hxs[h0]);
            ull hxb = pack2(hxs[h0 + 8], hxs[h0 + 8]);
            ull va  = pack2(vps[h0], vps[h0]);
            ull vb  = pack2(vps[h0 + 8], vps[h0 + 8]);
            #pragma unroll
            for (int ni = 0; ni < 4; ni++) {
                ull ya = add2(pack2(accr[mi][ni][0], accr[mi][ni][1]), hxa);
                ull yb = add2(pack2(accr[mi][ni][2], accr[mi][ni][3]), hxb);
                if (mi < 4) {
                    float l0, l1;
                    unpack2(ya, l0, l1);
                    s2[ni] = fma2(va, pack2(tanh_fast(l0), tanh_fast(l1)), s2[ni]);
                    unpack2(yb, l0, l1);
                    s2[ni] = fma2(vb, pack2(tanh_fast(l0), tanh_fast(l1)), s2[ni]);
                } else {
                    ull ua = mul2(ya, ya);
                    ull qa = fma2(ua, C7, C5);
                    qa = fma2(ua, qa, C3);
                    ull ta = fma2(mul2(ya, ua), qa, ya);
                    s2[ni] = fma2(va, ta, s2[ni]);

                    ull ub = mul2(yb, yb);
                    ull qb = fma2(ub, C7, C5);
                    qb = fma2(ub, qb, C3);
                    ull tb = fma2(mul2(yb, ub), qb, yb);
                    s2[ni] = fma2(vb, tb, s2[ni]);
                }
            }
        }

        // reduce over g (lane bits 2..4)
        float pl[4][2];
        #pragma unroll
        for (int ni = 0; ni < 4; ni++) unpack2(s2[ni], pl[ni][0], pl[ni][1]);
        #pragma unroll
        for (int off = 4; off < 32; off <<= 1)
            #pragma unroll
            for (int ni = 0; ni < 4; ni++)
                #pragma unroll
                for (int j = 0; j < 2; j++)
                    pl[ni][j] += __shfl_xor_sync(0xffffffff, pl[ni][j], off);

        if (g == 0) {
            #pragma unroll
            for (int ni = 0; ni < 4; ni++)
                ((float2*)(out + base))[ni * 4 + tc] =
                    make_float2(pl[ni][0], pl[ni][1]);
        }
        __syncwarp();

        // ---- last-arriver softmax for this batch row ----
        int b = tile >> 5;                 // 32 tiles per batch row
        int old = 0;
        if (lane == 0) {
            __threadfence();               // make tile logits visible
            old = atomicAdd(&g_cnt[b], 1);
        }
        old = __shfl_sync(0xffffffff, old, 0);
        if (old == 31) {
            __threadfence();               // acquire: see other blocks' logits
            float* row = out + b * 1024;
            float4 xv[8];
            float m = -3.4e38f;
            #pragma unroll
            for (int i = 0; i < 8; i++) {
                xv[i] = ((const float4*)row)[lane + i * 32];
                m = fmaxf(m, fmaxf(fmaxf(xv[i].x, xv[i].y),
                                   fmaxf(xv[i].z, xv[i].w)));
            }
            #pragma unroll
            for (int o = 16; o > 0; o >>= 1)
                m = fmaxf(m, __shfl_xor_sync(0xffffffff, m, o));
            float s = 0.f;
            #pragma unroll
            for (int i = 0; i < 8; i++) {
                xv[i].x = __expf(xv[i].x - m);
                xv[i].y = __expf(xv[i].y - m);
                xv[i].z = __expf(xv[i].z - m);
                xv[i].w = __expf(xv[i].w - m);
                s += xv[i].x + xv[i].y + xv[i].z + xv[i].w;
            }
            #pragma unroll
            for (int o = 16; o > 0; o >>= 1)
                s += __shfl_xor_sync(0xffffffff, s, o);
            float inv = 1.f / s;
            #pragma unroll
            for (int i = 0; i < 8; i++) {
                xv[i].x *= inv; xv[i].y *= inv;
                xv[i].z *= inv; xv[i].w *= inv;
                ((float4*)row)[lane + i * 32] = xv[i];
            }
            // v output for this row (batch-invariant value)
            float sv = hxs[lane] * Wval[lane]
                     + hxs[32 + lane] * Wval[32 + lane]
                     + hxs[64 + lane] * Wval[64 + lane]
                     + hxs[96 + lane] * Wval[96 + lane];
            #pragma unroll
            for (int o = 16; o > 0; o >>= 1)
                sv += __shfl_xor_sync(0xffffffff, sv, o);
            if (lane == 0) out[BN + b] = sv + bval[0];
        }
        __syncwarp();   // all lanes done with esw/xsw before next overwrite
    }
}

// ---------------------------------------------------------------------------
extern "C" void kernel_launch(void* const* d_in, const int* in_sizes, int n_in,
                              void* d_out, int out_size) {
    const float* nf     = (const float*)d_in[0];
    const float* Wemb   = (const float*)d_in[2];
    const float* bemb   = (const float*)d_in[3];
    const float* Wih    = (const float*)d_in[4];
    const float* bih    = (const float*)d_in[5];
    const float* bhh    = (const float*)d_in[7];
    const float* query  = (const float*)d_in[8];
    const float* Wattn  = (const float*)d_in[9];
    const float* vparam = (const float*)d_in[10];
    const float* Wval   = (const float*)d_in[11];
    const float* bval   = (const float*)d_in[12];
    float* out = (float*)d_out;

    static int smem_set = 0;
    const int smem_bytes = SM_FLOATS * 4;
    if (!smem_set) {
        cudaFuncSetAttribute(k_logits, cudaFuncAttributeMaxDynamicSharedMemorySize,
                             smem_bytes);
        smem_set = 1;
    }

    k_gh<<<32, 128>>>(Wih, bih, bhh, query);
    k_logits<<<GRID_LOGITS, 128, smem_bytes>>>(nf, Wemb, bemb, Wattn, vparam,
                                               Wval, bval, out);
}

// round 15
// speedup vs baseline: 1.2297x; 1.2297x over previous
#include <cuda_runtime.h>
#include <cuda_fp16.h>
#include <math.h>
#include <cstdint>

// Shapes: B=64, N=1024, F=4, H=128. BN = 65536 nodes.
// Output: pi [64,1024] then v [64,1] -> 65600 floats.
#define BN 65536
#define NT32 2048          // 32-node tiles
#define GRID_LOGITS 256    // x4 warps = 1024 -> exactly 2 tiles/warp

typedef unsigned long long ull;

__device__ float g_hx[128];

// ---------------- scalar helpers ----------------
__device__ __forceinline__ float tanh_fast(float x) {
    float r; asm("tanh.approx.f32 %0, %1;" : "=f"(r) : "f"(x)); return r;
}
// ---------------- packed f32x2 helpers ----------------
__device__ __forceinline__ ull pack2(float lo, float hi) {
    ull r; asm("mov.b64 %0, {%1, %2};" : "=l"(r) : "f"(lo), "f"(hi)); return r;
}
__device__ __forceinline__ void unpack2(ull p, float& lo, float& hi) {
    asm("mov.b64 {%0, %1}, %2;" : "=f"(lo), "=f"(hi) : "l"(p));
}
__device__ __forceinline__ ull fma2(ull a, ull b, ull c) {
    ull r; asm("fma.rn.f32x2 %0, %1, %2, %3;" : "=l"(r) : "l"(a), "l"(b), "l"(c)); return r;
}
__device__ __forceinline__ ull mul2(ull a, ull b) {
    ull r; asm("mul.rn.f32x2 %0, %1, %2;" : "=l"(r) : "l"(a), "l"(b)); return r;
}
__device__ __forceinline__ ull add2(ull a, ull b) {
    ull r; asm("add.rn.f32x2 %0, %1, %2;" : "=l"(r) : "l"(a), "l"(b)); return r;
}
// packed relu(fp32x2) -> half2 bits
__device__ __forceinline__ unsigned relu_h2(ull e, __half2 hz) {
    float lo, hi;
    unpack2(e, lo, hi);
    __half2 h = __hmax2(__floats2half2_rn(lo, hi), hz);
    return *reinterpret_cast<unsigned*>(&h);
}

// ---------------------------------------------------------------------------
// Kernel 0: fused gates + hx. 32 blocks x 128 threads; one warp per h index.
// Only gates i (row h), g (row 256+h), o (row 384+h) are needed (f*c0 = 0).
// ---------------------------------------------------------------------------
__global__ void k_gh(const float* __restrict__ Wih, const float* __restrict__ bih,
                     const float* __restrict__ bhh, const float* __restrict__ q) {
    int lane = threadIdx.x & 31, wid = threadIdx.x >> 5;
    int h = blockIdx.x * 4 + wid;
    float4 qv = __ldg((const float4*)q + lane);

    int rows[3] = {h, 256 + h, 384 + h};
    float acc[3];
    #pragma unroll
    for (int i = 0; i < 3; i++) {
        float4 wv = __ldg((const float4*)(Wih + rows[i] * 128) + lane);
        acc[i] = wv.x * qv.x + wv.y * qv.y + wv.z * qv.z + wv.w * qv.w;
    }
    #pragma unroll
    for (int o = 16; o > 0; o >>= 1)
        #pragma unroll
        for (int i = 0; i < 3; i++)
            acc[i] += __shfl_xor_sync(0xffffffff, acc[i], o);

    if (lane == 0) {
        float ig = acc[0] + bih[h] + bhh[h];
        float gg = acc[1] + bih[256 + h] + bhh[256 + h];
        float og = acc[2] + bih[384 + h] + bhh[384 + h];
        float si = 1.f / (1.f + __expf(-ig));
        float so = 1.f / (1.f + __expf(-og));
        float cx = si * tanh_fast(gg);
        g_hx[h] = so * tanh_fast(cx);
    }
}

// ---------------------------------------------------------------------------
// Kernel 1: logits, warp-autonomous 32n x 128h tiles, embedding FUSED into the
// GEMM k-loop: B fragments computed directly in registers (no es smem at all).
// Lane (g,tc) at (kt,ni) needs e_half2 for k2a=kt*8+tc, k2b=k2a+4, node ni*8+g.
// ---------------------------------------------------------------------------
#define AH_STRIDE 72
#define AS_OFF   0        // 128*72 half2 = 9216 float-slots
#define XS_OFF   9216     // 4 warps x 32 float4 = 512 floats
#define WPS_OFF  9728     // 64 k2 x 4 ull = 512 floats (packed W_emb row pairs)
#define BPS_OFF  10240    // 64 ull = 128 floats (packed b_emb pairs)
#define HXS_OFF  10368    // 128
#define VPS_OFF  10496    // 128
#define SM_FLOATS 10624   // 42.5 KB/CTA, x2 = 85 KB

__global__ __launch_bounds__(128, 2)
void k_logits(const float* __restrict__ nf, const float* __restrict__ Wemb,
              const float* __restrict__ bemb, const float* __restrict__ Wattn,
              const float* __restrict__ vparam, float* __restrict__ out) {
    extern __shared__ float sm[];
    __half2* as2 = (__half2*)sm;              // [128][72]
    ull* wps     = (ull*)(sm + WPS_OFF);      // [64][4]
    ull* bps     = (ull*)(sm + BPS_OFF);      // [64]
    float* hxs   = sm + HXS_OFF;
    float* vps   = sm + VPS_OFF;

    int t = threadIdx.x;
    int lane = t & 31, w = t >> 5;
    int g = lane >> 2, tc = lane & 3;

    float4* xsw = (float4*)(sm + XS_OFF) + w * 32;

    // ---- one-time staging: A = half2(W_attn), permuted k-pair columns ----
    for (int i = t * 4; i < 16384; i += 512) {
        float4 wv = *(const float4*)(Wattn + i);
        int h = i >> 7, k = i & 127;
        int k2 = k >> 1;
        int kb8 = k2 & ~7, j = k2 & 7;       // j in {0,2,4,6}
        int c1 = kb8 + ((j < 4) ? 2 * j : 2 * j - 7);
        as2[h * AH_STRIDE + c1]     = __floats2half2_rn(wv.x, wv.y);
        as2[h * AH_STRIDE + c1 + 2] = __floats2half2_rn(wv.z, wv.w);
    }
    // packed W_emb / b_emb: pair rows (2k2, 2k2+1)
    if (t < 64) {
        int k2 = t;
        #pragma unroll
        for (int f = 0; f < 4; f++)
            wps[k2 * 4 + f] = pack2(Wemb[(2 * k2) * 4 + f],
                                    Wemb[(2 * k2 + 1) * 4 + f]);
        bps[k2] = pack2(bemb[2 * k2], bemb[2 * k2 + 1]);
    }
    hxs[t] = g_hx[t];
    vps[t] = vparam[t];

    const ull C3 = pack2(-0.3333333333f, -0.3333333333f);
    const ull C5 = pack2(0.1333333333f, 0.1333333333f);
    const ull C7 = pack2(-0.0539682540f, -0.0539682540f);
    const __half2 hzero = __floats2half2_rn(0.f, 0.f);

    __syncthreads();   // staging complete (only block-wide sync)

    int gw = blockIdx.x * 4 + w;       // global warp id: 0..1023
    for (int tile = gw; tile < NT32; tile += GRID_LOGITS * 4) {
        int base = tile * 32;

        // ---- node features: warp loads 32, lane keeps its 4 nodes packed ----
        xsw[lane] = __ldg((const float4*)nf + (base + lane));
        __syncwarp();
        ull xp[4][4];
        #pragma unroll
        for (int ni = 0; ni < 4; ni++) {
            float4 x = xsw[ni * 8 + g];
            xp[ni][0] = pack2(x.x, x.x);
            xp[ni][1] = pack2(x.y, x.y);
            xp[ni][2] = pack2(x.z, x.z);
            xp[ni][3] = pack2(x.w, x.w);
        }
        __syncwarp();   // reads done before next tile's overwrite

        // ---- fused embed + fp16 GEMM: warp tile 128h x 32n ----
        float accr[8][4][4];
        #pragma unroll
        for (int mi = 0; mi < 8; mi++)
            #pragma unroll
            for (int ni = 0; ni < 4; ni++)
                #pragma unroll
                for (int j = 0; j < 4; j++) accr[mi][ni][j] = 0.f;

        #pragma unroll
        for (int kt = 0; kt < 8; kt++) {
            int k2a = kt * 8 + tc;
            int k2b = k2a + 4;
            // packed embedding weights for this lane's two k2 (broadcast LDS)
            ull wa0 = wps[k2a * 4], wa1 = wps[k2a * 4 + 1];
            ull wa2 = wps[k2a * 4 + 2], wa3 = wps[k2a * 4 + 3];
            ull ba = bps[k2a];
            ull wb0 = wps[k2b * 4], wb1 = wps[k2b * 4 + 1];
            ull wb2 = wps[k2b * 4 + 2], wb3 = wps[k2b * 4 + 3];
            ull bb = bps[k2b];

            // B fragments for 4 node-groups, computed in registers
            uint2 bfr[4];
            #pragma unroll
            for (int ni = 0; ni < 4; ni++) {
                ull ea = ba;
                ea = fma2(xp[ni][0], wa0, ea);
                ea = fma2(xp[ni][1], wa1, ea);
                ea = fma2(xp[ni][2], wa2, ea);
                ea = fma2(xp[ni][3], wa3, ea);
                ull eb = bb;
                eb = fma2(xp[ni][0], wb0, eb);
                eb = fma2(xp[ni][1], wb1, eb);
                eb = fma2(xp[ni][2], wb2, eb);
                eb = fma2(xp[ni][3], wb3, eb);
                bfr[ni].x = relu_h2(ea, hzero);
                bfr[ni].y = relu_h2(eb, hzero);
            }

            int cb = kt * 8 + 2 * tc;
            #pragma unroll
            for (int mi = 0; mi < 8; mi++) {
                int r = mi * 16 + g;
                uint2 alo = *(const uint2*)(as2 + r * AH_STRIDE + cb);
                uint2 ahi = *(const uint2*)(as2 + (r + 8) * AH_STRIDE + cb);
                #pragma unroll
                for (int ni = 0; ni < 4; ni++) {
                    asm volatile(
                        "mma.sync.aligned.m16n8k16.row.col.f32.f16.f16.f32 "
                        "{%0,%1,%2,%3}, {%4,%5,%6,%7}, {%8,%9}, {%0,%1,%2,%3};"
                        : "+f"(accr[mi][ni][0]), "+f"(accr[mi][ni][1]),
                          "+f"(accr[mi][ni][2]), "+f"(accr[mi][ni][3])
                        : "r"(alo.x), "r"(ahi.x), "r"(alo.y), "r"(ahi.y),
                          "r"(bfr[ni].x), "r"(bfr[ni].y));
                }
            }
        }

        // ---- epilogue: v-weighted tanh, h-sum fully warp-internal ----
        ull s2[4];
        #pragma unroll
        for (int ni = 0; ni < 4; ni++) s2[ni] = pack2(0.f, 0.f);
        #pragma unroll
        for (int mi = 0; mi < 8; mi++) {
            int h0 = mi * 16 + g;
            ull hxa = pack2(hxs[h0], hxs[h0]);
            ull hxb = pack2(hxs[h0 + 8], hxs[h0 + 8]);
            ull va  = pack2(vps[h0], vps[h0]);
            ull vb  = pack2(vps[h0 + 8], vps[h0 + 8]);
            #pragma unroll
            for (int ni = 0; ni < 4; ni++) {
                ull ya = add2(pack2(accr[mi][ni][0], accr[mi][ni][1]), hxa);
                ull yb = add2(pack2(accr[mi][ni][2], accr[mi][ni][3]), hxb);
                if (mi < 4) {
                    float l0, l1;
                    unpack2(ya, l0, l1);
                    s2[ni] = fma2(va, pack2(tanh_fast(l0), tanh_fast(l1)), s2[ni]);
                    unpack2(yb, l0, l1);
                    s2[ni] = fma2(vb, pack2(tanh_fast(l0), tanh_fast(l1)), s2[ni]);
                } else {
                    ull ua = mul2(ya, ya);
                    ull qa = fma2(ua, C7, C5);
                    qa = fma2(ua, qa, C3);
                    ull ta = fma2(mul2(ya, ua), qa, ya);
                    s2[ni] = fma2(va, ta, s2[ni]);

                    ull ub = mul2(yb, yb);
                    ull qb = fma2(ub, C7, C5);
                    qb = fma2(ub, qb, C3);
                    ull tb = fma2(mul2(yb, ub), qb, yb);
                    s2[ni] = fma2(vb, tb, s2[ni]);
                }
            }
        }

        // reduce over g (lane bits 2..4)
        float pl[4][2];
        #pragma unroll
        for (int ni = 0; ni < 4; ni++) unpack2(s2[ni], pl[ni][0], pl[ni][1]);
        #pragma unroll
        for (int off = 4; off < 32; off <<= 1)
            #pragma unroll
            for (int ni = 0; ni < 4; ni++)
                #pragma unroll
                for (int j = 0; j < 2; j++)
                    pl[ni][j] += __shfl_xor_sync(0xffffffff, pl[ni][j], off);

        if (g == 0) {
            #pragma unroll
            for (int ni = 0; ni < 4; ni++)
                ((float2*)(out + base))[ni * 4 + tc] =
                    make_float2(pl[ni][0], pl[ni][1]);
        }
    }
}

// ---------------------------------------------------------------------------
// Kernel 2: softmax over N=1024 per batch (blocks 0..63) + v output (block 64).
// ---------------------------------------------------------------------------
__global__ void k_softmax(const float* __restrict__ Wval,
                          const float* __restrict__ bval,
                          float* __restrict__ out) {
    __shared__ float wred[8];
    __shared__ float bcast[2];
    int b = blockIdx.x;
    int t = threadIdx.x;
    int lane = t & 31, wid = t >> 5;

    if (b == 64) {
        if (wid == 0) {
            float s = g_hx[lane] * Wval[lane]
                    + g_hx[32 + lane] * Wval[32 + lane]
                    + g_hx[64 + lane] * Wval[64 + lane]
                    + g_hx[96 + lane] * Wval[96 + lane];
            #pragma unroll
            for (int o = 16; o > 0; o >>= 1)
                s += __shfl_xor_sync(0xffffffff, s, o);
            float v = s + bval[0];
            out[BN + lane] = v;
            out[BN + 32 + lane] = v;
        }
        return;
    }

    float* row = out + b * 1024;
    float4 x = ((const float4*)row)[t];
    float m = fmaxf(fmaxf(x.x, x.y), fmaxf(x.z, x.w));
    #pragma unroll
    for (int o = 16; o > 0; o >>= 1)
        m = fmaxf(m, __shfl_xor_sync(0xffffffff, m, o));
    if (lane == 0) wred[wid] = m;
    __syncthreads();
    if (wid == 0) {
        float mm = wred[lane & 7];
        #pragma unroll
        for (int o = 4; o > 0; o >>= 1)
            mm = fmaxf(mm, __shfl_xor_sync(0xffffffff, mm, o));
        if (lane == 0) bcast[0] = mm;
    }
    __syncthreads();
    float M = bcast[0];
    float e0 = __expf(x.x - M);
    float e1 = __expf(x.y - M);
    float e2 = __expf(x.z - M);
    float e3 = __expf(x.w - M);
    float s = e0 + e1 + e2 + e3;
    #pragma unroll
    for (int o = 16; o > 0; o >>= 1)
        s += __shfl_xor_sync(0xffffffff, s, o);
    if (lane == 0) wred[wid] = s;
    __syncthreads();
    if (wid == 0) {
        float ss = wred[lane & 7];
        #pragma unroll
        for (int o = 4; o > 0; o >>= 1)
            ss += __shfl_xor_sync(0xffffffff, ss, o);
        if (lane == 0) bcast[1] = ss;
    }
    __syncthreads();
    float inv = 1.f / bcast[1];
    float4 r;
    r.x = e0 * inv; r.y = e1 * inv; r.z = e2 * inv; r.w = e3 * inv;
    ((float4*)row)[t] = r;
}

// ---------------------------------------------------------------------------
extern "C" void kernel_launch(void* const* d_in, const int* in_sizes, int n_in,
                              void* d_out, int out_size) {
    const float* nf     = (const float*)d_in[0];
    const float* Wemb   = (const float*)d_in[2];
    const float* bemb   = (const float*)d_in[3];
    const float* Wih    = (const float*)d_in[4];
    const float* bih    = (const float*)d_in[5];
    const float* bhh    = (const float*)d_in[7];
    const float* query  = (const float*)d_in[8];
    const float* Wattn  = (const float*)d_in[9];
    const float* vparam = (const float*)d_in[10];
    const float* Wval   = (const float*)d_in[11];
    const float* bval   = (const float*)d_in[12];
    float* out = (float*)d_out;

    static int smem_set = 0;
    const int smem_bytes = SM_FLOATS * 4;
    if (!smem_set) {
        cudaFuncSetAttribute(k_logits, cudaFuncAttributeMaxDynamicSharedMemorySize,
                             smem_bytes);
        smem_set = 1;
    }

    k_gh<<<32, 128>>>(Wih, bih, bhh, query);
    k_logits<<<GRID_LOGITS, 128, smem_bytes>>>(nf, Wemb, bemb, Wattn, vparam, out);
    k_softmax<<<65, 256>>>(Wval, bval, out);
}